// round 4
// baseline (speedup 1.0000x reference)
#include <cuda_runtime.h>

#define D 128
#define MAXN 50176
#define LN_EPS 1e-5f

// Scratch buffers (device globals — allocation is forbidden). Declared as
// float4 so 16B alignment is guaranteed for vector loads/stores/reductions.
__device__ float4 g_agg4[(size_t)MAXN * (D / 4)];
__device__ float4 g_buf4[(size_t)MAXN * (D / 4)];

// ---------------------------------------------------------------------------
// Zero the aggregation buffer (vectorized).
// ---------------------------------------------------------------------------
__global__ void zero_agg_kernel(int n4) {
    int i = blockIdx.x * blockDim.x + threadIdx.x;
    if (i < n4) g_agg4[i] = make_float4(0.f, 0.f, 0.f, 0.f);
}

// ---------------------------------------------------------------------------
// Scatter-add: one warp per edge, each lane owns one float4 (128 floats/row).
// x rows are L2-resident (25.6MB << 126MB L2). Reduction uses
// red.global.add.v4.f32 (sm_90+) to quarter the L2 atomic-op count.
// edge_index is int32 (JAX x64 disabled downcasts the int64 request).
// ---------------------------------------------------------------------------
__global__ void scatter_kernel(const float* __restrict__ x,
                               const int* __restrict__ ei,
                               int E) {
    int w = blockIdx.x * (blockDim.x >> 5) + (threadIdx.x >> 5);
    int lane = threadIdx.x & 31;
    if (w >= E) return;
    int s = __ldg(ei + w);       // sender   (uniform within warp)
    int r = __ldg(ei + E + w);   // receiver
    float4 v = ((const float4*)(x + (size_t)s * D))[lane];
    float4* dst = g_agg4 + (size_t)r * (D / 4) + lane;
    asm volatile("red.global.add.v4.f32 [%0], {%1,%2,%3,%4};"
                 :: "l"(dst), "f"(v.x), "f"(v.y), "f"(v.z), "f"(v.w)
                 : "memory");
}

// ---------------------------------------------------------------------------
// Buffer selection. sel: 0 = passed pointer, 1 = g_agg, 2 = g_buf
// ---------------------------------------------------------------------------
__device__ __forceinline__ const float* pick_src(const float* p, int sel) {
    if (sel == 1) return (const float*)g_agg4;
    if (sel == 2) return (const float*)g_buf4;
    return p;
}
__device__ __forceinline__ float* pick_dst(float* p, int sel) {
    if (sel == 1) return (float*)g_agg4;
    if (sel == 2) return (float*)g_buf4;
    return p;
}

// ---------------------------------------------------------------------------
// Fused GEMM + bias + (ReLU | LayerNorm):  out[N,128] = act(A @ W + bias)
// KSTAGES = Ktotal/64. KSTAGES==4 means K=256 with A = concat(A0, A1):
//   stages 0,1 read A0 cols [0:64),[64:128); stages 2,3 read A1 likewise.
// Tile: 64 rows x 128 cols per CTA, 256 threads (8 warps).
//   warp ty owns rows [ty*8, ty*8+8); lane tx owns cols [tx*4, tx*4+4).
// A loads are warp-uniform (all lanes same row) -> broadcast LDG.128.
// W staged 64 k-rows (32KB) in smem. LN: each output row lives in one
// warp -> shuffle reduction, no extra pass over memory.
// ---------------------------------------------------------------------------
template<int KSTAGES, bool RELU, bool LN>
__global__ void __launch_bounds__(256)
gemm_kernel(const float* __restrict__ A0p, int a0sel,
            const float* __restrict__ A1p, int a1sel,
            const float* __restrict__ W, const float* __restrict__ bias,
            const float* __restrict__ gamma, const float* __restrict__ beta,
            float* __restrict__ outp, int osel, int N) {
    __shared__ float Ws[64 * D];

    const float* A0 = pick_src(A0p, a0sel);
    const float* A1 = pick_src(A1p, a1sel);
    float* out = pick_dst(outp, osel);

    int tx = threadIdx.x & 31;
    int ty = threadIdx.x >> 5;
    int rowBase = blockIdx.x * 64 + ty * 8;

    int offs[8];
#pragma unroll
    for (int r = 0; r < 8; ++r) {
        int rw = rowBase + r;
        if (rw > N - 1) rw = N - 1;   // clamp: loads stay in-bounds, stores guarded
        offs[r] = rw * D;
    }

    float acc[8][4];
#pragma unroll
    for (int r = 0; r < 8; ++r)
#pragma unroll
        for (int c = 0; c < 4; ++c) acc[r][c] = 0.f;

    for (int s = 0; s < KSTAGES; ++s) {
        // Stage 64 k-rows of W into smem (coalesced float4).
        const float4* Wg = (const float4*)(W + s * 64 * D);
        float4* Wsv = (float4*)Ws;
#pragma unroll
        for (int i = 0; i < 8; ++i)
            Wsv[threadIdx.x + i * 256] = Wg[threadIdx.x + i * 256];
        __syncthreads();

        const float* A = (KSTAGES == 4 && s >= 2) ? A1 : A0;
        int coff = (KSTAGES == 4) ? (s & 1) * 64 : s * 64;

#pragma unroll
        for (int kc = 0; kc < 64; kc += 4) {
            float4 b0 = *(const float4*)(Ws + (kc + 0) * D + tx * 4);
            float4 b1 = *(const float4*)(Ws + (kc + 1) * D + tx * 4);
            float4 b2 = *(const float4*)(Ws + (kc + 2) * D + tx * 4);
            float4 b3 = *(const float4*)(Ws + (kc + 3) * D + tx * 4);
#pragma unroll
            for (int r = 0; r < 8; ++r) {
                float4 a = *(const float4*)(A + offs[r] + coff + kc);
                acc[r][0] += a.x * b0.x; acc[r][1] += a.x * b0.y;
                acc[r][2] += a.x * b0.z; acc[r][3] += a.x * b0.w;
                acc[r][0] += a.y * b1.x; acc[r][1] += a.y * b1.y;
                acc[r][2] += a.y * b1.z; acc[r][3] += a.y * b1.w;
                acc[r][0] += a.z * b2.x; acc[r][1] += a.z * b2.y;
                acc[r][2] += a.z * b2.z; acc[r][3] += a.z * b2.w;
                acc[r][0] += a.w * b3.x; acc[r][1] += a.w * b3.y;
                acc[r][2] += a.w * b3.z; acc[r][3] += a.w * b3.w;
            }
        }
        __syncthreads();
    }

    // Bias + activation
    float4 bb = ((const float4*)bias)[tx];
#pragma unroll
    for (int r = 0; r < 8; ++r) {
        acc[r][0] += bb.x; acc[r][1] += bb.y;
        acc[r][2] += bb.z; acc[r][3] += bb.w;
        if (RELU) {
            acc[r][0] = fmaxf(acc[r][0], 0.f);
            acc[r][1] = fmaxf(acc[r][1], 0.f);
            acc[r][2] = fmaxf(acc[r][2], 0.f);
            acc[r][3] = fmaxf(acc[r][3], 0.f);
        }
    }

    if (LN) {
        float4 gv = ((const float4*)gamma)[tx];
        float4 bv = ((const float4*)beta)[tx];
#pragma unroll
        for (int r = 0; r < 8; ++r) {
            float s1 = acc[r][0] + acc[r][1] + acc[r][2] + acc[r][3];
            float s2 = acc[r][0] * acc[r][0] + acc[r][1] * acc[r][1] +
                       acc[r][2] * acc[r][2] + acc[r][3] * acc[r][3];
#pragma unroll
            for (int o = 16; o > 0; o >>= 1) {
                s1 += __shfl_xor_sync(0xffffffffu, s1, o);
                s2 += __shfl_xor_sync(0xffffffffu, s2, o);
            }
            float mu  = s1 * (1.0f / 128.0f);
            float var = s2 * (1.0f / 128.0f) - mu * mu;
            float inv = rsqrtf(var + LN_EPS);
            acc[r][0] = (acc[r][0] - mu) * inv * gv.x + bv.x;
            acc[r][1] = (acc[r][1] - mu) * inv * gv.y + bv.y;
            acc[r][2] = (acc[r][2] - mu) * inv * gv.z + bv.z;
            acc[r][3] = (acc[r][3] - mu) * inv * gv.w + bv.w;
        }
    }

#pragma unroll
    for (int r = 0; r < 8; ++r) {
        int rw = rowBase + r;
        if (rw < N)
            *(float4*)(out + rw * D + tx * 4) =
                make_float4(acc[r][0], acc[r][1], acc[r][2], acc[r][3]);
    }
}

// ---------------------------------------------------------------------------
// kernel_launch: zero agg -> scatter -> 4 fused GEMMs (last + LN)
// Ping-pong: agg -> buf(h1) -> agg(h2) -> buf(h3) -> d_out
// ---------------------------------------------------------------------------
extern "C" void kernel_launch(void* const* d_in, const int* in_sizes, int n_in,
                              void* d_out, int out_size) {
    const float* x     = (const float*)d_in[0];
    const int*   ei    = (const int*)d_in[1];     // int32 (JAX x64 off)
    const float* W1    = (const float*)d_in[2];
    const float* b1    = (const float*)d_in[3];
    const float* W2    = (const float*)d_in[4];
    const float* b2    = (const float*)d_in[5];
    const float* W3    = (const float*)d_in[6];
    const float* b3    = (const float*)d_in[7];
    const float* W4    = (const float*)d_in[8];
    const float* b4    = (const float*)d_in[9];
    const float* gamma = (const float*)d_in[10];
    const float* beta  = (const float*)d_in[11];
    float* out = (float*)d_out;

    int N = in_sizes[0] / D;
    int E = in_sizes[1] / 2;

    // 1. zero aggregation buffer
    int n4 = N * (D / 4);
    zero_agg_kernel<<<(n4 + 255) / 256, 256>>>(n4);

    // 2. scatter-add (one warp per edge, 8 warps per block)
    int nblk = (E + 7) / 8;
    scatter_kernel<<<nblk, 256>>>(x, ei, E);

    // 3-6. MLP layers (64 rows per CTA)
    int gb = (N + 63) / 64;
    // h1 = relu([x, agg] @ W1 + b1)          -> g_buf
    gemm_kernel<4, true,  false><<<gb, 256>>>(x, 0, nullptr, 1, W1, b1,
                                              nullptr, nullptr, nullptr, 2, N);
    // h2 = relu(h1 @ W2 + b2)                -> g_agg
    gemm_kernel<2, true,  false><<<gb, 256>>>(nullptr, 2, nullptr, 0, W2, b2,
                                              nullptr, nullptr, nullptr, 1, N);
    // h3 = relu(h2 @ W3 + b3)                -> g_buf
    gemm_kernel<2, true,  false><<<gb, 256>>>(nullptr, 1, nullptr, 0, W3, b3,
                                              nullptr, nullptr, nullptr, 2, N);
    // out = LN(h3 @ W4 + b4) * gamma + beta  -> d_out
    gemm_kernel<2, false, true ><<<gb, 256>>>(nullptr, 2, nullptr, 0, W4, b4,
                                              gamma, beta, out, 0, N);
}

// round 5
// speedup vs baseline: 1.0425x; 1.0425x over previous
#include <cuda_runtime.h>

#define D 128
#define MAXN 50176
#define LN_EPS 1e-5f

// Scratch buffers (device globals — allocation is forbidden). Declared as
// float4 so 16B alignment is guaranteed for vector loads/stores/reductions.
__device__ float4 g_agg4[(size_t)MAXN * (D / 4)];
__device__ float4 g_buf4[(size_t)MAXN * (D / 4)];

// ---------------------------------------------------------------------------
// Zero the aggregation buffer (vectorized).
// ---------------------------------------------------------------------------
__global__ void zero_agg_kernel(int n4) {
    int i = blockIdx.x * blockDim.x + threadIdx.x;
    if (i < n4) g_agg4[i] = make_float4(0.f, 0.f, 0.f, 0.f);
}

// ---------------------------------------------------------------------------
// Scatter-add: one warp per edge, each lane owns one float4 (128 floats/row).
// x rows are L2-resident (25.6MB << 126MB L2). Reduction uses
// red.global.add.v4.f32 (sm_90+) to quarter the L2 atomic-op count.
// edge_index is int32 (JAX x64 disabled downcasts the int64 request).
// ---------------------------------------------------------------------------
__global__ void scatter_kernel(const float* __restrict__ x,
                               const int* __restrict__ ei,
                               int E) {
    int w = blockIdx.x * (blockDim.x >> 5) + (threadIdx.x >> 5);
    int lane = threadIdx.x & 31;
    if (w >= E) return;
    int s = __ldg(ei + w);       // sender   (uniform within warp)
    int r = __ldg(ei + E + w);   // receiver
    float4 v = ((const float4*)(x + (size_t)s * D))[lane];
    float4* dst = g_agg4 + (size_t)r * (D / 4) + lane;
    asm volatile("red.global.add.v4.f32 [%0], {%1,%2,%3,%4};"
                 :: "l"(dst), "f"(v.x), "f"(v.y), "f"(v.z), "f"(v.w)
                 : "memory");
}

// ---------------------------------------------------------------------------
// Buffer selection. sel: 0 = passed pointer, 1 = g_agg, 2 = g_buf
// ---------------------------------------------------------------------------
__device__ __forceinline__ const float* pick_src(const float* p, int sel) {
    if (sel == 1) return (const float*)g_agg4;
    if (sel == 2) return (const float*)g_buf4;
    return p;
}
__device__ __forceinline__ float* pick_dst(float* p, int sel) {
    if (sel == 1) return (float*)g_agg4;
    if (sel == 2) return (float*)g_buf4;
    return p;
}

// ---------------------------------------------------------------------------
// Fused GEMM + bias + (ReLU | LayerNorm):  out[N,128] = act(A @ W + bias)
// KSTAGES = Ktotal/64. KSTAGES==4 means K=256 with A = concat(A0, A1):
//   stages 0,1 read A0 cols [0:64),[64:128); stages 2,3 read A1 likewise.
// Tile: 64 rows x 128 cols per CTA, 256 threads (8 warps).
//   warp ty owns rows [ty*8, ty*8+8); lane tx owns cols [tx*4, tx*4+4).
// A loads are warp-uniform (all lanes same row) -> broadcast LDG.128.
// W staged 64 k-rows (32KB) in smem. LN: each output row lives in one
// warp -> shuffle reduction, no extra pass over memory.
// ---------------------------------------------------------------------------
template<int KSTAGES, bool RELU, bool LN>
__global__ void __launch_bounds__(256)
gemm_kernel(const float* __restrict__ A0p, int a0sel,
            const float* __restrict__ A1p, int a1sel,
            const float* __restrict__ W, const float* __restrict__ bias,
            const float* __restrict__ gamma, const float* __restrict__ beta,
            float* __restrict__ outp, int osel, int N) {
    __shared__ float Ws[64 * D];

    const float* A0 = pick_src(A0p, a0sel);
    const float* A1 = pick_src(A1p, a1sel);
    float* out = pick_dst(outp, osel);

    int tx = threadIdx.x & 31;
    int ty = threadIdx.x >> 5;
    int rowBase = blockIdx.x * 64 + ty * 8;

    int offs[8];
#pragma unroll
    for (int r = 0; r < 8; ++r) {
        int rw = rowBase + r;
        if (rw > N - 1) rw = N - 1;   // clamp: loads stay in-bounds, stores guarded
        offs[r] = rw * D;
    }

    float acc[8][4];
#pragma unroll
    for (int r = 0; r < 8; ++r)
#pragma unroll
        for (int c = 0; c < 4; ++c) acc[r][c] = 0.f;

    for (int s = 0; s < KSTAGES; ++s) {
        // Stage 64 k-rows of W into smem (coalesced float4).
        const float4* Wg = (const float4*)(W + s * 64 * D);
        float4* Wsv = (float4*)Ws;
#pragma unroll
        for (int i = 0; i < 8; ++i)
            Wsv[threadIdx.x + i * 256] = Wg[threadIdx.x + i * 256];
        __syncthreads();

        const float* A = (KSTAGES == 4 && s >= 2) ? A1 : A0;
        int coff = (KSTAGES == 4) ? (s & 1) * 64 : s * 64;

#pragma unroll
        for (int kc = 0; kc < 64; kc += 4) {
            float4 b0 = *(const float4*)(Ws + (kc + 0) * D + tx * 4);
            float4 b1 = *(const float4*)(Ws + (kc + 1) * D + tx * 4);
            float4 b2 = *(const float4*)(Ws + (kc + 2) * D + tx * 4);
            float4 b3 = *(const float4*)(Ws + (kc + 3) * D + tx * 4);
#pragma unroll
            for (int r = 0; r < 8; ++r) {
                float4 a = *(const float4*)(A + offs[r] + coff + kc);
                acc[r][0] += a.x * b0.x; acc[r][1] += a.x * b0.y;
                acc[r][2] += a.x * b0.z; acc[r][3] += a.x * b0.w;
                acc[r][0] += a.y * b1.x; acc[r][1] += a.y * b1.y;
                acc[r][2] += a.y * b1.z; acc[r][3] += a.y * b1.w;
                acc[r][0] += a.z * b2.x; acc[r][1] += a.z * b2.y;
                acc[r][2] += a.z * b2.z; acc[r][3] += a.z * b2.w;
                acc[r][0] += a.w * b3.x; acc[r][1] += a.w * b3.y;
                acc[r][2] += a.w * b3.z; acc[r][3] += a.w * b3.w;
            }
        }
        __syncthreads();
    }

    // Bias + activation
    float4 bb = ((const float4*)bias)[tx];
#pragma unroll
    for (int r = 0; r < 8; ++r) {
        acc[r][0] += bb.x; acc[r][1] += bb.y;
        acc[r][2] += bb.z; acc[r][3] += bb.w;
        if (RELU) {
            acc[r][0] = fmaxf(acc[r][0], 0.f);
            acc[r][1] = fmaxf(acc[r][1], 0.f);
            acc[r][2] = fmaxf(acc[r][2], 0.f);
            acc[r][3] = fmaxf(acc[r][3], 0.f);
        }
    }

    if (LN) {
        float4 gv = ((const float4*)gamma)[tx];
        float4 bv = ((const float4*)beta)[tx];
#pragma unroll
        for (int r = 0; r < 8; ++r) {
            float s1 = acc[r][0] + acc[r][1] + acc[r][2] + acc[r][3];
            float s2 = acc[r][0] * acc[r][0] + acc[r][1] * acc[r][1] +
                       acc[r][2] * acc[r][2] + acc[r][3] * acc[r][3];
#pragma unroll
            for (int o = 16; o > 0; o >>= 1) {
                s1 += __shfl_xor_sync(0xffffffffu, s1, o);
                s2 += __shfl_xor_sync(0xffffffffu, s2, o);
            }
            float mu  = s1 * (1.0f / 128.0f);
            float var = s2 * (1.0f / 128.0f) - mu * mu;
            float inv = rsqrtf(var + LN_EPS);
            acc[r][0] = (acc[r][0] - mu) * inv * gv.x + bv.x;
            acc[r][1] = (acc[r][1] - mu) * inv * gv.y + bv.y;
            acc[r][2] = (acc[r][2] - mu) * inv * gv.z + bv.z;
            acc[r][3] = (acc[r][3] - mu) * inv * gv.w + bv.w;
        }
    }

#pragma unroll
    for (int r = 0; r < 8; ++r) {
        int rw = rowBase + r;
        if (rw < N)
            *(float4*)(out + rw * D + tx * 4) =
                make_float4(acc[r][0], acc[r][1], acc[r][2], acc[r][3]);
    }
}

// ---------------------------------------------------------------------------
// kernel_launch: zero agg -> scatter -> 4 fused GEMMs (last + LN)
// Ping-pong: agg -> buf(h1) -> agg(h2) -> buf(h3) -> d_out
// ---------------------------------------------------------------------------
extern "C" void kernel_launch(void* const* d_in, const int* in_sizes, int n_in,
                              void* d_out, int out_size) {
    const float* x     = (const float*)d_in[0];
    const int*   ei    = (const int*)d_in[1];     // int32 (JAX x64 off)
    const float* W1    = (const float*)d_in[2];
    const float* b1    = (const float*)d_in[3];
    const float* W2    = (const float*)d_in[4];
    const float* b2    = (const float*)d_in[5];
    const float* W3    = (const float*)d_in[6];
    const float* b3    = (const float*)d_in[7];
    const float* W4    = (const float*)d_in[8];
    const float* b4    = (const float*)d_in[9];
    const float* gamma = (const float*)d_in[10];
    const float* beta  = (const float*)d_in[11];
    float* out = (float*)d_out;

    int N = in_sizes[0] / D;
    int E = in_sizes[1] / 2;

    // 1. zero aggregation buffer
    int n4 = N * (D / 4);
    zero_agg_kernel<<<(n4 + 255) / 256, 256>>>(n4);

    // 2. scatter-add (one warp per edge, 8 warps per block)
    int nblk = (E + 7) / 8;
    scatter_kernel<<<nblk, 256>>>(x, ei, E);

    // 3-6. MLP layers (64 rows per CTA)
    int gb = (N + 63) / 64;
    // h1 = relu([x, agg] @ W1 + b1)          -> g_buf
    gemm_kernel<4, true,  false><<<gb, 256>>>(x, 0, nullptr, 1, W1, b1,
                                              nullptr, nullptr, nullptr, 2, N);
    // h2 = relu(h1 @ W2 + b2)                -> g_agg
    gemm_kernel<2, true,  false><<<gb, 256>>>(nullptr, 2, nullptr, 0, W2, b2,
                                              nullptr, nullptr, nullptr, 1, N);
    // h3 = relu(h2 @ W3 + b3)                -> g_buf
    gemm_kernel<2, true,  false><<<gb, 256>>>(nullptr, 1, nullptr, 0, W3, b3,
                                              nullptr, nullptr, nullptr, 2, N);
    // out = LN(h3 @ W4 + b4) * gamma + beta  -> d_out
    gemm_kernel<2, false, true ><<<gb, 256>>>(nullptr, 2, nullptr, 0, W4, b4,
                                              gamma, beta, out, 0, N);
}

// round 12
// speedup vs baseline: 1.6447x; 1.5776x over previous
#include <cuda_runtime.h>
#include <cuda_bf16.h>
#include <cstdint>

#define D 128
#define MAXN 50176
#define LN_EPS 1e-5f

// ---------------------------------------------------------------------------
// Device scratch (allocation forbidden -> __device__ globals, uint4 = 16B align)
// ---------------------------------------------------------------------------
__device__ float4 g_agg4[(size_t)MAXN * (D / 4)];      // fp32 aggregation
__device__ uint4  g_aHi[(size_t)MAXN * 32];            // bf16 plane, up to 256 cols
__device__ uint4  g_aLo[(size_t)MAXN * 32];
__device__ uint4  g_bHi[(size_t)MAXN * 16];            // bf16 plane, 128 cols
__device__ uint4  g_bLo[(size_t)MAXN * 16];
__device__ uint4  g_w1h[4096], g_w1l[4096];            // W1^T [128][256] bf16
__device__ uint4  g_w2h[2048], g_w2l[2048];            // W^T  [128][128] bf16
__device__ uint4  g_w3h[2048], g_w3l[2048];
__device__ uint4  g_w4h[2048], g_w4l[2048];

// ---------------------------------------------------------------------------
// PTX helpers (base ISA only: cp.async, ldmatrix, mma.sync — NO tcgen05)
// ---------------------------------------------------------------------------
__device__ __forceinline__ uint32_t smem_u32(const void* p) {
    uint32_t a;
    asm("{ .reg .u64 t; cvta.to.shared.u64 t, %1; cvt.u32.u64 %0, t; }"
        : "=r"(a) : "l"(p));
    return a;
}
#define CP_ASYNC16(s, g) \
    asm volatile("cp.async.cg.shared.global [%0], [%1], 16;" :: "r"(s), "l"(g))
#define CP_COMMIT() asm volatile("cp.async.commit_group;")
#define CP_WAIT0()  asm volatile("cp.async.wait_group 0;" ::: "memory")
#define LDSM4(r, a) \
    asm volatile("ldmatrix.sync.aligned.m8n8.x4.shared.b16 {%0,%1,%2,%3}, [%4];" \
                 : "=r"((r)[0]), "=r"((r)[1]), "=r"((r)[2]), "=r"((r)[3]) : "r"(a))
#define MMA16816(c, a, b0, b1) \
    asm volatile("mma.sync.aligned.m16n8k16.row.col.f32.bf16.bf16.f32 " \
                 "{%0,%1,%2,%3},{%4,%5,%6,%7},{%8,%9},{%0,%1,%2,%3};" \
                 : "+f"((c)[0]), "+f"((c)[1]), "+f"((c)[2]), "+f"((c)[3]) \
                 : "r"((a)[0]), "r"((a)[1]), "r"((a)[2]), "r"((a)[3]), \
                   "r"(b0), "r"(b1))

__device__ __forceinline__ void bsplit(float v, __nv_bfloat16& h, __nv_bfloat16& l) {
    h = __float2bfloat16(v);
    l = __float2bfloat16(v - __bfloat162float(h));
}
__device__ __forceinline__ uint32_t pack2(__nv_bfloat16 a, __nv_bfloat16 b) {
    return (uint32_t)__bfloat16_as_ushort(a) |
           ((uint32_t)__bfloat16_as_ushort(b) << 16);
}

// ---------------------------------------------------------------------------
// zero agg / scatter (unchanged, known-good)
// ---------------------------------------------------------------------------
__global__ void zero_agg_kernel(int n4) {
    int i = blockIdx.x * blockDim.x + threadIdx.x;
    if (i < n4) g_agg4[i] = make_float4(0.f, 0.f, 0.f, 0.f);
}

__global__ void scatter_kernel(const float* __restrict__ x,
                               const int* __restrict__ ei, int E) {
    int w = blockIdx.x * (blockDim.x >> 5) + (threadIdx.x >> 5);
    int lane = threadIdx.x & 31;
    if (w >= E) return;
    int s = __ldg(ei + w);
    int r = __ldg(ei + E + w);
    float4 v = ((const float4*)(x + (size_t)s * D))[lane];
    float4* dst = g_agg4 + (size_t)r * (D / 4) + lane;
    asm volatile("red.global.add.v4.f32 [%0], {%1,%2,%3,%4};"
                 :: "l"(dst), "f"(v.x), "f"(v.y), "f"(v.z), "f"(v.w)
                 : "memory");
}

// ---------------------------------------------------------------------------
// W prep: hi/lo planes of W^T  ([n][k] layout, k-contiguous)
// ---------------------------------------------------------------------------
__global__ void wprep_kernel(const float* __restrict__ W, int widx, int K) {
    int i = blockIdx.x * blockDim.x + threadIdx.x;
    if (i >= 128 * K) return;
    int n = i / K, k = i - n * K;
    __nv_bfloat16 h, l;
    bsplit(__ldg(W + k * 128 + n), h, l);
    __nv_bfloat16* oh;
    __nv_bfloat16* ol;
    switch (widx) {
        case 1: oh = (__nv_bfloat16*)g_w1h; ol = (__nv_bfloat16*)g_w1l; break;
        case 2: oh = (__nv_bfloat16*)g_w2h; ol = (__nv_bfloat16*)g_w2l; break;
        case 3: oh = (__nv_bfloat16*)g_w3h; ol = (__nv_bfloat16*)g_w3l; break;
        default: oh = (__nv_bfloat16*)g_w4h; ol = (__nv_bfloat16*)g_w4l; break;
    }
    oh[i] = h; ol[i] = l;
}

// ---------------------------------------------------------------------------
// split [x | agg] -> hi/lo bf16 planes [PADN][256] (zero rows >= N)
// ---------------------------------------------------------------------------
__global__ void split_kernel(const float* __restrict__ x, int N, int PADN) {
    int i = blockIdx.x * blockDim.x + threadIdx.x;
    if (i >= PADN * 64) return;
    int r = i >> 6;
    int c4 = (i & 63) * 4;
    float4 v = make_float4(0.f, 0.f, 0.f, 0.f);
    if (r < N) {
        const float* src = (c4 < 128)
            ? (x + (size_t)r * 128 + c4)
            : ((const float*)g_agg4 + (size_t)r * 128 + (c4 - 128));
        v = *(const float4*)src;
    }
    __nv_bfloat16 h0, l0, h1, l1, h2, l2, h3, l3;
    bsplit(v.x, h0, l0); bsplit(v.y, h1, l1);
    bsplit(v.z, h2, l2); bsplit(v.w, h3, l3);
    size_t off = (size_t)r * 256 + c4;
    *(uint2*)((__nv_bfloat16*)g_aHi + off) = make_uint2(pack2(h0, h1), pack2(h2, h3));
    *(uint2*)((__nv_bfloat16*)g_aLo + off) = make_uint2(pack2(l0, l1), pack2(l2, l3));
}

// ---------------------------------------------------------------------------
// Stage a 128x64 bf16 tile (row-major, strideElems) into swizzled smem.
// Swizzle: 128B rows, 16B chunk index XOR (row & 7).
// ---------------------------------------------------------------------------
__device__ __forceinline__ void load_tile(uint32_t sbase,
                                          const __nv_bfloat16* __restrict__ g,
                                          int strideElems, int tid) {
#pragma unroll
    for (int i = 0; i < 4; ++i) {
        int c = tid + i * 256;
        int row = c >> 3;
        int col8 = c & 7;
        uint32_t off = row * 128 + col8 * 16;
        uint32_t sw = off ^ ((off >> 3) & 0x70);
        CP_ASYNC16(sbase + sw, g + (size_t)row * strideElems + col8 * 8);
    }
}

// ---------------------------------------------------------------------------
// bf16x3 mma.sync GEMM: out = act(A @ W + bias), 128x128 tile per CTA.
// 8 warps (4x2): warp = 32 rows x 64 cols. K in 64-chunks.
// asel: 1 = a planes (stride KCH*64), 2 = b planes. osel: 1/2 planes, 0 = fp32+LN.
// ---------------------------------------------------------------------------
#define SM_AH 0
#define SM_AL 16384
#define SM_WH 32768
#define SM_WL 49152
#define SMEM_BYTES 65536

template<int KCH, bool LN>
__global__ void __launch_bounds__(256, 2)
gemm_mma(int asel, int wsel, const float* __restrict__ bias,
         const float* __restrict__ gamma, const float* __restrict__ beta,
         float* __restrict__ outf, int osel, int N) {
    extern __shared__ char smem[];
    uint32_t sbase = smem_u32(smem);
    const int tid = threadIdx.x;
    const int lane = tid & 31, wid = tid >> 5;
    const int wm = wid >> 1, wn = wid & 1;
    const int warpRow = wm * 32;
    const int g = lane >> 2, t = lane & 3;
    const int K = KCH * 64;
    const int row0 = blockIdx.x * 128;

    const __nv_bfloat16* Ah = (asel == 1) ? (const __nv_bfloat16*)g_aHi
                                          : (const __nv_bfloat16*)g_bHi;
    const __nv_bfloat16* Al = (asel == 1) ? (const __nv_bfloat16*)g_aLo
                                          : (const __nv_bfloat16*)g_bLo;
    const __nv_bfloat16* Wh;
    const __nv_bfloat16* Wl;
    switch (wsel) {
        case 1: Wh = (const __nv_bfloat16*)g_w1h; Wl = (const __nv_bfloat16*)g_w1l; break;
        case 2: Wh = (const __nv_bfloat16*)g_w2h; Wl = (const __nv_bfloat16*)g_w2l; break;
        case 3: Wh = (const __nv_bfloat16*)g_w3h; Wl = (const __nv_bfloat16*)g_w3l; break;
        default: Wh = (const __nv_bfloat16*)g_w4h; Wl = (const __nv_bfloat16*)g_w4l; break;
    }

    // ldmatrix per-lane address components (swizzle mask is row-dependent only)
    int aOff[2], aMask[2];
#pragma unroll
    for (int mt = 0; mt < 2; ++mt) {
        int r = warpRow + mt * 16 + (lane & 15);
        aOff[mt] = r * 128;
        aMask[mt] = (r & 7) << 4;
    }
    int wOff[4], wMask[4];
#pragma unroll
    for (int j = 0; j < 4; ++j) {
        int r = wn * 64 + j * 16 + ((lane >> 4) & 1) * 8 + (lane & 7);
        wOff[j] = r * 128;
        wMask[j] = (r & 7) << 4;
    }

    float acc[2][8][4];
#pragma unroll
    for (int mt = 0; mt < 2; ++mt)
#pragma unroll
        for (int nt = 0; nt < 8; ++nt)
#pragma unroll
            for (int k = 0; k < 4; ++k) acc[mt][nt][k] = 0.f;

    for (int ch = 0; ch < KCH; ++ch) {
        load_tile(sbase + SM_AH, Ah + (size_t)row0 * K + ch * 64, K, tid);
        load_tile(sbase + SM_AL, Al + (size_t)row0 * K + ch * 64, K, tid);
        load_tile(sbase + SM_WH, Wh + ch * 64, K, tid);
        load_tile(sbase + SM_WL, Wl + ch * 64, K, tid);
        CP_COMMIT();
        CP_WAIT0();
        __syncthreads();

#pragma unroll
        for (int ks = 0; ks < 4; ++ks) {
            int kbA = ks * 32 + (lane & 16);
            int kbB = ks * 32 + ((lane & 8) << 1);
            uint32_t ah[2][4], al[2][4];
#pragma unroll
            for (int mt = 0; mt < 2; ++mt) {
                LDSM4(ah[mt], sbase + SM_AH + aOff[mt] + (kbA ^ aMask[mt]));
                LDSM4(al[mt], sbase + SM_AL + aOff[mt] + (kbA ^ aMask[mt]));
            }
#pragma unroll
            for (int j = 0; j < 4; ++j) {
                uint32_t wh[4], wl[4];
                uint32_t aw = wOff[j] + (kbB ^ wMask[j]);
                LDSM4(wh, sbase + SM_WH + aw);
                LDSM4(wl, sbase + SM_WL + aw);
#pragma unroll
                for (int mt = 0; mt < 2; ++mt) {
                    MMA16816(acc[mt][j * 2 + 0], ah[mt], wh[0], wh[1]);
                    MMA16816(acc[mt][j * 2 + 1], ah[mt], wh[2], wh[3]);
                    MMA16816(acc[mt][j * 2 + 0], ah[mt], wl[0], wl[1]);
                    MMA16816(acc[mt][j * 2 + 1], ah[mt], wl[2], wl[3]);
                    MMA16816(acc[mt][j * 2 + 0], al[mt], wh[0], wh[1]);
                    MMA16816(acc[mt][j * 2 + 1], al[mt], wh[2], wh[3]);
                }
            }
        }
        __syncthreads();
    }

    // ---- epilogue ----
    float bv[8][2];
#pragma unroll
    for (int nt = 0; nt < 8; ++nt) {
        int c = wn * 64 + nt * 8 + 2 * t;
        bv[nt][0] = __ldg(bias + c);
        bv[nt][1] = __ldg(bias + c + 1);
    }

    if (!LN) {
        __nv_bfloat16* oH = (osel == 1) ? (__nv_bfloat16*)g_aHi : (__nv_bfloat16*)g_bHi;
        __nv_bfloat16* oL = (osel == 1) ? (__nv_bfloat16*)g_aLo : (__nv_bfloat16*)g_bLo;
#pragma unroll
        for (int mt = 0; mt < 2; ++mt)
#pragma unroll
            for (int h = 0; h < 2; ++h) {
                int gr = row0 + warpRow + mt * 16 + g + h * 8;
#pragma unroll
                for (int nt = 0; nt < 8; ++nt) {
                    int c = wn * 64 + nt * 8 + 2 * t;
                    float v0 = fmaxf(acc[mt][nt][h * 2 + 0] + bv[nt][0], 0.f);
                    float v1 = fmaxf(acc[mt][nt][h * 2 + 1] + bv[nt][1], 0.f);
                    __nv_bfloat16 h0, l0, h1, l1;
                    bsplit(v0, h0, l0);
                    bsplit(v1, h1, l1);
                    *(uint32_t*)(oH + (size_t)gr * 128 + c) = pack2(h0, h1);
                    *(uint32_t*)(oL + (size_t)gr * 128 + c) = pack2(l0, l1);
                }
            }
    } else {
        // per-row partial sums over this warp's 64 cols, reduce over lane group
        float* ps = (float*)smem;   // [128 rows][2 wn][2]  = 2KB (tiles done)
#pragma unroll
        for (int mt = 0; mt < 2; ++mt)
#pragma unroll
            for (int h = 0; h < 2; ++h) {
                float s1 = 0.f, s2 = 0.f;
#pragma unroll
                for (int nt = 0; nt < 8; ++nt) {
                    float v0 = acc[mt][nt][h * 2 + 0] + bv[nt][0];
                    float v1 = acc[mt][nt][h * 2 + 1] + bv[nt][1];
                    s1 += v0 + v1;
                    s2 += v0 * v0 + v1 * v1;
                }
                s1 += __shfl_xor_sync(0xffffffffu, s1, 1);
                s2 += __shfl_xor_sync(0xffffffffu, s2, 1);
                s1 += __shfl_xor_sync(0xffffffffu, s1, 2);
                s2 += __shfl_xor_sync(0xffffffffu, s2, 2);
                if (t == 0) {
                    int r = warpRow + mt * 16 + g + h * 8;
                    ps[r * 4 + wn * 2 + 0] = s1;
                    ps[r * 4 + wn * 2 + 1] = s2;
                }
            }
        __syncthreads();

        float gv[8][2], betv[8][2];
#pragma unroll
        for (int nt = 0; nt < 8; ++nt) {
            int c = wn * 64 + nt * 8 + 2 * t;
            gv[nt][0] = __ldg(gamma + c);     gv[nt][1] = __ldg(gamma + c + 1);
            betv[nt][0] = __ldg(beta + c);    betv[nt][1] = __ldg(beta + c + 1);
        }
#pragma unroll
        for (int mt = 0; mt < 2; ++mt)
#pragma unroll
            for (int h = 0; h < 2; ++h) {
                int r = warpRow + mt * 16 + g + h * 8;
                int gr = row0 + r;
                float S1 = ps[r * 4 + 0] + ps[r * 4 + 2];
                float S2 = ps[r * 4 + 1] + ps[r * 4 + 3];
                float mu = S1 * (1.0f / 128.0f);
                float var = S2 * (1.0f / 128.0f) - mu * mu;
                float inv = rsqrtf(var + LN_EPS);
                if (gr < N) {
#pragma unroll
                    for (int nt = 0; nt < 8; ++nt) {
                        int c = wn * 64 + nt * 8 + 2 * t;
                        float v0 = acc[mt][nt][h * 2 + 0] + bv[nt][0];
                        float v1 = acc[mt][nt][h * 2 + 1] + bv[nt][1];
                        float2 o;
                        o.x = (v0 - mu) * inv * gv[nt][0] + betv[nt][0];
                        o.y = (v1 - mu) * inv * gv[nt][1] + betv[nt][1];
                        *(float2*)(outf + (size_t)gr * 128 + c) = o;
                    }
                }
            }
    }
}

// ---------------------------------------------------------------------------
// kernel_launch
// ---------------------------------------------------------------------------
extern "C" void kernel_launch(void* const* d_in, const int* in_sizes, int n_in,
                              void* d_out, int out_size) {
    const float* x     = (const float*)d_in[0];
    const int*   ei    = (const int*)d_in[1];
    const float* W1    = (const float*)d_in[2];
    const float* b1    = (const float*)d_in[3];
    const float* W2    = (const float*)d_in[4];
    const float* b2    = (const float*)d_in[5];
    const float* W3    = (const float*)d_in[6];
    const float* b3    = (const float*)d_in[7];
    const float* W4    = (const float*)d_in[8];
    const float* b4    = (const float*)d_in[9];
    const float* gamma = (const float*)d_in[10];
    const float* beta  = (const float*)d_in[11];
    float* out = (float*)d_out;

    int N = in_sizes[0] / D;
    int E = in_sizes[1] / 2;
    int PADN = ((N + 127) / 128) * 128;
    int GB = PADN / 128;

    cudaFuncSetAttribute(gemm_mma<4, false>, cudaFuncAttributeMaxDynamicSharedMemorySize, SMEM_BYTES);
    cudaFuncSetAttribute(gemm_mma<2, false>, cudaFuncAttributeMaxDynamicSharedMemorySize, SMEM_BYTES);
    cudaFuncSetAttribute(gemm_mma<2, true >, cudaFuncAttributeMaxDynamicSharedMemorySize, SMEM_BYTES);

    // 1. zero agg
    int n4 = N * (D / 4);
    zero_agg_kernel<<<(n4 + 255) / 256, 256>>>(n4);

    // 2. scatter
    scatter_kernel<<<(E + 7) / 8, 256>>>(x, ei, E);

    // 3. W^T hi/lo planes
    wprep_kernel<<<(128 * 256 + 255) / 256, 256>>>(W1, 1, 256);
    wprep_kernel<<<(128 * 128 + 255) / 256, 256>>>(W2, 2, 128);
    wprep_kernel<<<(128 * 128 + 255) / 256, 256>>>(W3, 3, 128);
    wprep_kernel<<<(128 * 128 + 255) / 256, 256>>>(W4, 4, 128);

    // 4. split/pack [x | agg] -> a planes (stride 256)
    split_kernel<<<(PADN * 64 + 255) / 256, 256>>>(x, N, PADN);

    // 5-8. MLP: a(256) -> b -> a -> b -> d_out (+LN)
    gemm_mma<4, false><<<GB, 256, SMEM_BYTES>>>(1, 1, b1, nullptr, nullptr, nullptr, 2, N);
    gemm_mma<2, false><<<GB, 256, SMEM_BYTES>>>(2, 2, b2, nullptr, nullptr, nullptr, 1, N);
    gemm_mma<2, false><<<GB, 256, SMEM_BYTES>>>(1, 3, b3, nullptr, nullptr, nullptr, 2, N);
    gemm_mma<2, true ><<<GB, 256, SMEM_BYTES>>>(2, 4, b4, gamma, beta, out, 0, N);
}

// round 13
// speedup vs baseline: 1.9221x; 1.1687x over previous
#include <cuda_runtime.h>
#include <cuda_bf16.h>
#include <cstdint>

#define D 128
#define MAXN 50176
#define LN_EPS 1e-5f

// ---------------------------------------------------------------------------
// Device scratch (allocation forbidden -> __device__ globals, uint4 = 16B align)
// ---------------------------------------------------------------------------
__device__ float4 g_agg4[(size_t)MAXN * (D / 4)];      // fp32 aggregation
__device__ uint4  g_w1h[4096], g_w1l[4096];            // W1^T [128][256] bf16 planes
__device__ uint4  g_w2h[2048], g_w2l[2048];            // W^T  [128][128]
__device__ uint4  g_w3h[2048], g_w3l[2048];
__device__ uint4  g_w4h[2048], g_w4l[2048];

// ---------------------------------------------------------------------------
// PTX helpers (base ISA only: cp.async, ldmatrix, mma.sync — NO tcgen05)
// ---------------------------------------------------------------------------
__device__ __forceinline__ uint32_t smem_u32(const void* p) {
    uint32_t a;
    asm("{ .reg .u64 t; cvta.to.shared.u64 t, %1; cvt.u32.u64 %0, t; }"
        : "=r"(a) : "l"(p));
    return a;
}
#define CP_ASYNC16(s, g) \
    asm volatile("cp.async.cg.shared.global [%0], [%1], 16;" :: "r"(s), "l"(g))
#define CP_COMMIT() asm volatile("cp.async.commit_group;")
#define CP_WAIT0()  asm volatile("cp.async.wait_group 0;" ::: "memory")
#define CP_WAIT1()  asm volatile("cp.async.wait_group 1;" ::: "memory")
#define LDSM4(r, a) \
    asm volatile("ldmatrix.sync.aligned.m8n8.x4.shared.b16 {%0,%1,%2,%3}, [%4];" \
                 : "=r"((r)[0]), "=r"((r)[1]), "=r"((r)[2]), "=r"((r)[3]) : "r"(a))
#define MMA16816(c, a, b0, b1) \
    asm volatile("mma.sync.aligned.m16n8k16.row.col.f32.bf16.bf16.f32 " \
                 "{%0,%1,%2,%3},{%4,%5,%6,%7},{%8,%9},{%0,%1,%2,%3};" \
                 : "+f"((c)[0]), "+f"((c)[1]), "+f"((c)[2]), "+f"((c)[3]) \
                 : "r"((a)[0]), "r"((a)[1]), "r"((a)[2]), "r"((a)[3]), \
                   "r"(b0), "r"(b1))

__device__ __forceinline__ void bsplit(float v, __nv_bfloat16& h, __nv_bfloat16& l) {
    h = __float2bfloat16(v);
    l = __float2bfloat16(v - __bfloat162float(h));
}
__device__ __forceinline__ uint32_t pack2(__nv_bfloat16 a, __nv_bfloat16 b) {
    return (uint32_t)__bfloat16_as_ushort(a) |
           ((uint32_t)__bfloat16_as_ushort(b) << 16);
}

// ---------------------------------------------------------------------------
// zero agg / scatter (unchanged, known-good)
// ---------------------------------------------------------------------------
__global__ void zero_agg_kernel(int n4) {
    int i = blockIdx.x * blockDim.x + threadIdx.x;
    if (i < n4) g_agg4[i] = make_float4(0.f, 0.f, 0.f, 0.f);
}

__global__ void scatter_kernel(const float* __restrict__ x,
                               const int* __restrict__ ei, int E) {
    int w = blockIdx.x * (blockDim.x >> 5) + (threadIdx.x >> 5);
    int lane = threadIdx.x & 31;
    if (w >= E) return;
    int s = __ldg(ei + w);
    int r = __ldg(ei + E + w);
    float4 v = ((const float4*)(x + (size_t)s * D))[lane];
    float4* dst = g_agg4 + (size_t)r * (D / 4) + lane;
    asm volatile("red.global.add.v4.f32 [%0], {%1,%2,%3,%4};"
                 :: "l"(dst), "f"(v.x), "f"(v.y), "f"(v.z), "f"(v.w)
                 : "memory");
}

// ---------------------------------------------------------------------------
// Fused W prep: all four W^T hi/lo planes in one launch.
// region 0: W1 (128x256), regions 1-3: W2..W4 (128x128)
// ---------------------------------------------------------------------------
__global__ void wprep_all(const float* __restrict__ W1, const float* __restrict__ W2,
                          const float* __restrict__ W3, const float* __restrict__ W4) {
    int i = blockIdx.x * blockDim.x + threadIdx.x;
    const float* W;
    __nv_bfloat16 *oh, *ol;
    int n, k, K, j;
    if (i < 32768) {                   // W1: n*256 + k
        W = W1; K = 256; j = i;
        oh = (__nv_bfloat16*)g_w1h; ol = (__nv_bfloat16*)g_w1l;
    } else {
        int r = i - 32768;
        int wsel = r >> 14;            // 0..2
        if (wsel > 2) return;
        j = r & 16383; K = 128;
        switch (wsel) {
            case 0: W = W2; oh = (__nv_bfloat16*)g_w2h; ol = (__nv_bfloat16*)g_w2l; break;
            case 1: W = W3; oh = (__nv_bfloat16*)g_w3h; ol = (__nv_bfloat16*)g_w3l; break;
            default: W = W4; oh = (__nv_bfloat16*)g_w4h; ol = (__nv_bfloat16*)g_w4l; break;
        }
    }
    n = j / K; k = j - n * K;
    __nv_bfloat16 h, l;
    bsplit(__ldg(W + k * 128 + n), h, l);
    oh[j] = h; ol[j] = l;
}

// ---------------------------------------------------------------------------
// Stage a 128x64 bf16 tile (row-major, strideElems) into swizzled smem.
// ---------------------------------------------------------------------------
__device__ __forceinline__ void load_tile(uint32_t sdst,
                                          const __nv_bfloat16* __restrict__ g,
                                          int strideElems, int tid) {
#pragma unroll
    for (int i = 0; i < 4; ++i) {
        int c = tid + i * 256;
        int row = c >> 3;
        int col8 = c & 7;
        uint32_t off = row * 128 + col8 * 16;
        uint32_t sw = off ^ ((off >> 3) & 0x70);
        CP_ASYNC16(sdst + sw, g + (size_t)row * strideElems + col8 * 8);
    }
}

// ---------------------------------------------------------------------------
// Fused 4-layer MLP, one 128-row tile per CTA, activations live in smem.
// smem: A chunks 0..3 (hi+lo 16KB each = 32KB/chunk) @ 0..128KB
//       W ping-pong bufs (32KB each)                 @ 128KB..192KB
// ---------------------------------------------------------------------------
#define SM_W  131072
#define SMEM_BYTES 196608

__global__ void __launch_bounds__(256, 1)
mlp_fused(const float* __restrict__ x,
          const float* __restrict__ b1, const float* __restrict__ b2,
          const float* __restrict__ b3, const float* __restrict__ b4,
          const float* __restrict__ gamma, const float* __restrict__ beta,
          float* __restrict__ outf, int N) {
    extern __shared__ char smem[];
    uint32_t sbase = smem_u32(smem);
    const int tid = threadIdx.x;
    const int lane = tid & 31, wid = tid >> 5;
    const int wm = wid >> 1, wn = wid & 1;
    const int warpRow = wm * 32;
    const int g = lane >> 2, t = lane & 3;
    const int row0 = blockIdx.x * 128;

    const __nv_bfloat16* WH[4] = {(const __nv_bfloat16*)g_w1h, (const __nv_bfloat16*)g_w2h,
                                  (const __nv_bfloat16*)g_w3h, (const __nv_bfloat16*)g_w4h};
    const __nv_bfloat16* WL[4] = {(const __nv_bfloat16*)g_w1l, (const __nv_bfloat16*)g_w2l,
                                  (const __nv_bfloat16*)g_w3l, (const __nv_bfloat16*)g_w4l};
    const float* BS[4] = {b1, b2, b3, b4};
    const int KK[4]  = {256, 128, 128, 128};
    const int KCH[4] = {4, 2, 2, 2};

    // ldmatrix per-lane address components (verbatim from working R12 kernel)
    int aOff[2], aMask[2];
#pragma unroll
    for (int mt = 0; mt < 2; ++mt) {
        int r = warpRow + mt * 16 + (lane & 15);
        aOff[mt] = r * 128;
        aMask[mt] = (r & 7) << 4;
    }
    int wOff[4], wMask[4];
#pragma unroll
    for (int j = 0; j < 4; ++j) {
        int r = wn * 64 + j * 16 + ((lane >> 4) & 1) * 8 + (lane & 7);
        wOff[j] = r * 128;
        wMask[j] = (r & 7) << 4;
    }

    // Issue first W chunk (layer 0, chunk 0) -> buf 0, overlaps prologue.
    load_tile(sbase + SM_W,         WH[0], 256, tid);
    load_tile(sbase + SM_W + 16384, WL[0], 256, tid);
    CP_COMMIT();

    // Prologue: [x | agg] fp32 -> bf16 hi/lo planes, A chunks 0..3 (swizzled).
#pragma unroll
    for (int ch = 0; ch < 4; ++ch) {
        const float* src = (ch < 2) ? x : (const float*)g_agg4;
        int colBase = (ch & 1) * 64;
#pragma unroll
        for (int j = 0; j < 8; ++j) {
            int pos = tid + j * 256;             // 0..2047
            int row = pos >> 4;
            int c4 = (pos & 15) * 4;
            int gr = row0 + row;
            float4 v = make_float4(0.f, 0.f, 0.f, 0.f);
            if (gr < N) v = *(const float4*)(src + (size_t)gr * 128 + colBase + c4);
            __nv_bfloat16 h0, l0, h1, l1, h2, l2, h3, l3;
            bsplit(v.x, h0, l0); bsplit(v.y, h1, l1);
            bsplit(v.z, h2, l2); bsplit(v.w, h3, l3);
            uint32_t off = row * 128 + c4 * 2;
            uint32_t sw = off ^ ((off >> 3) & 0x70);
            *(uint2*)(smem + ch * 32768 + sw) = make_uint2(pack2(h0, h1), pack2(h2, h3));
            *(uint2*)(smem + ch * 32768 + 16384 + sw) = make_uint2(pack2(l0, l1), pack2(l2, l3));
        }
    }

    float acc[2][8][4];
#pragma unroll
    for (int mt = 0; mt < 2; ++mt)
#pragma unroll
        for (int nt = 0; nt < 8; ++nt)
#pragma unroll
            for (int k = 0; k < 4; ++k) acc[mt][nt][k] = 0.f;

    for (int L = 0; L < 4; ++L) {
        const int kch = KCH[L];
        for (int ch = 0; ch < kch; ++ch) {
            // Prefetch next chunk (within layer, or next layer's chunk 0).
            int nL = L, nch = ch + 1;
            if (nch == kch) { nL = L + 1; nch = 0; }
            if (nL < 4) {
                uint32_t wb = sbase + SM_W + ((ch + 1) & 1) * 32768;
                load_tile(wb,         WH[nL] + nch * 64, KK[nL], tid);
                load_tile(wb + 16384, WL[nL] + nch * 64, KK[nL], tid);
                CP_COMMIT();
                CP_WAIT1();
            } else {
                CP_WAIT0();
            }
            __syncthreads();

            uint32_t offA = sbase + ch * 32768;
            uint32_t offW = sbase + SM_W + (ch & 1) * 32768;
#pragma unroll
            for (int ks = 0; ks < 4; ++ks) {
                int kbA = ks * 32 + (lane & 16);
                int kbB = ks * 32 + ((lane & 8) << 1);
                uint32_t ah[2][4], al[2][4];
#pragma unroll
                for (int mt = 0; mt < 2; ++mt) {
                    LDSM4(ah[mt], offA + aOff[mt] + (kbA ^ aMask[mt]));
                    LDSM4(al[mt], offA + 16384 + aOff[mt] + (kbA ^ aMask[mt]));
                }
#pragma unroll
                for (int j = 0; j < 4; ++j) {
                    uint32_t wh[4], wl[4];
                    uint32_t aw = wOff[j] + (kbB ^ wMask[j]);
                    LDSM4(wh, offW + aw);
                    LDSM4(wl, offW + 16384 + aw);
#pragma unroll
                    for (int mt = 0; mt < 2; ++mt) {
                        MMA16816(acc[mt][j * 2 + 0], ah[mt], wh[0], wh[1]);
                        MMA16816(acc[mt][j * 2 + 1], ah[mt], wh[2], wh[3]);
                        MMA16816(acc[mt][j * 2 + 0], ah[mt], wl[0], wl[1]);
                        MMA16816(acc[mt][j * 2 + 1], ah[mt], wl[2], wl[3]);
                        MMA16816(acc[mt][j * 2 + 0], al[mt], wh[0], wh[1]);
                        MMA16816(acc[mt][j * 2 + 1], al[mt], wh[2], wh[3]);
                    }
                }
            }
            __syncthreads();   // all reads of A and this W buf complete
        }

        // Bias for this layer (warp's 64 cols)
        float bv[8][2];
#pragma unroll
        for (int nt = 0; nt < 8; ++nt) {
            int c = wn * 64 + nt * 8 + 2 * t;
            bv[nt][0] = BS[L][c];
            bv[nt][1] = BS[L][c + 1];
        }

        if (L < 3) {
            // bias + ReLU, split, write back into A chunks 0/1 (chunk = wn).
#pragma unroll
            for (int mt = 0; mt < 2; ++mt)
#pragma unroll
                for (int h = 0; h < 2; ++h) {
                    int r = warpRow + mt * 16 + g + h * 8;
#pragma unroll
                    for (int nt = 0; nt < 8; ++nt) {
                        int cc = nt * 8 + 2 * t;         // col within chunk
                        float v0 = fmaxf(acc[mt][nt][h * 2 + 0] + bv[nt][0], 0.f);
                        float v1 = fmaxf(acc[mt][nt][h * 2 + 1] + bv[nt][1], 0.f);
                        __nv_bfloat16 h0, l0, h1, l1;
                        bsplit(v0, h0, l0);
                        bsplit(v1, h1, l1);
                        uint32_t off = r * 128 + cc * 2;
                        uint32_t sw = off ^ ((off >> 3) & 0x70);
                        *(uint32_t*)(smem + wn * 32768 + sw) = pack2(h0, h1);
                        *(uint32_t*)(smem + wn * 32768 + 16384 + sw) = pack2(l0, l1);
                    }
                }
            // reset acc for next layer
#pragma unroll
            for (int mt = 0; mt < 2; ++mt)
#pragma unroll
                for (int nt = 0; nt < 8; ++nt)
#pragma unroll
                    for (int k = 0; k < 4; ++k) acc[mt][nt][k] = 0.f;
            // next layer's first chunk wait+sync orders these writes before reads
        } else {
            // LayerNorm epilogue -> fp32 out
            float* ps = (float*)(smem + SM_W);   // W bufs dead after last sync
#pragma unroll
            for (int mt = 0; mt < 2; ++mt)
#pragma unroll
                for (int h = 0; h < 2; ++h) {
                    float s1 = 0.f, s2 = 0.f;
#pragma unroll
                    for (int nt = 0; nt < 8; ++nt) {
                        float v0 = acc[mt][nt][h * 2 + 0] + bv[nt][0];
                        float v1 = acc[mt][nt][h * 2 + 1] + bv[nt][1];
                        s1 += v0 + v1;
                        s2 += v0 * v0 + v1 * v1;
                    }
                    s1 += __shfl_xor_sync(0xffffffffu, s1, 1);
                    s2 += __shfl_xor_sync(0xffffffffu, s2, 1);
                    s1 += __shfl_xor_sync(0xffffffffu, s1, 2);
                    s2 += __shfl_xor_sync(0xffffffffu, s2, 2);
                    if (t == 0) {
                        int r = warpRow + mt * 16 + g + h * 8;
                        ps[r * 4 + wn * 2 + 0] = s1;
                        ps[r * 4 + wn * 2 + 1] = s2;
                    }
                }
            __syncthreads();

            float gv[8][2], betv[8][2];
#pragma unroll
            for (int nt = 0; nt < 8; ++nt) {
                int c = wn * 64 + nt * 8 + 2 * t;
                gv[nt][0] = gamma[c];   gv[nt][1] = gamma[c + 1];
                betv[nt][0] = beta[c];  betv[nt][1] = beta[c + 1];
            }
#pragma unroll
            for (int mt = 0; mt < 2; ++mt)
#pragma unroll
                for (int h = 0; h < 2; ++h) {
                    int r = warpRow + mt * 16 + g + h * 8;
                    int gr = row0 + r;
                    float S1 = ps[r * 4 + 0] + ps[r * 4 + 2];
                    float S2 = ps[r * 4 + 1] + ps[r * 4 + 3];
                    float mu = S1 * (1.0f / 128.0f);
                    float var = S2 * (1.0f / 128.0f) - mu * mu;
                    float inv = rsqrtf(var + LN_EPS);
                    if (gr < N) {
#pragma unroll
                        for (int nt = 0; nt < 8; ++nt) {
                            int c = wn * 64 + nt * 8 + 2 * t;
                            float v0 = acc[mt][nt][h * 2 + 0] + bv[nt][0];
                            float v1 = acc[mt][nt][h * 2 + 1] + bv[nt][1];
                            float2 o;
                            o.x = (v0 - mu) * inv * gv[nt][0] + betv[nt][0];
                            o.y = (v1 - mu) * inv * gv[nt][1] + betv[nt][1];
                            *(float2*)(outf + (size_t)gr * 128 + c) = o;
                        }
                    }
                }
        }
    }
}

// ---------------------------------------------------------------------------
// kernel_launch: zero -> scatter -> wprep_all -> fused MLP   (4 launches)
// ---------------------------------------------------------------------------
extern "C" void kernel_launch(void* const* d_in, const int* in_sizes, int n_in,
                              void* d_out, int out_size) {
    const float* x     = (const float*)d_in[0];
    const int*   ei    = (const int*)d_in[1];
    const float* W1    = (const float*)d_in[2];
    const float* b1    = (const float*)d_in[3];
    const float* W2    = (const float*)d_in[4];
    const float* b2    = (const float*)d_in[5];
    const float* W3    = (const float*)d_in[6];
    const float* b3    = (const float*)d_in[7];
    const float* W4    = (const float*)d_in[8];
    const float* b4    = (const float*)d_in[9];
    const float* gamma = (const float*)d_in[10];
    const float* beta  = (const float*)d_in[11];
    float* out = (float*)d_out;

    int N = in_sizes[0] / D;
    int E = in_sizes[1] / 2;
    int GB = (N + 127) / 128;

    cudaFuncSetAttribute(mlp_fused, cudaFuncAttributeMaxDynamicSharedMemorySize, SMEM_BYTES);

    int n4 = N * (D / 4);
    zero_agg_kernel<<<(n4 + 255) / 256, 256>>>(n4);
    scatter_kernel<<<(E + 7) / 8, 256>>>(x, ei, E);
    wprep_all<<<(32768 + 3 * 16384 + 255) / 256, 256>>>(W1, W2, W3, W4);
    mlp_fused<<<GB, 256, SMEM_BYTES>>>(x, b1, b2, b3, b4, gamma, beta, out, N);
}